// round 3
// baseline (speedup 1.0000x reference)
#include <cuda_runtime.h>
#include <cuda_bf16.h>

// loss = -sum_i logp[i, target[i]] * reward[i]
//   logp:   (N, V) float32, N = 5728, V = 9487  (~217 MB)
//   reward: (N,)   float32
//   target: int64 OR int32 (JAX x64 ambiguity) -> runtime width detect
//
// R2 finding: tail (threadfence + 45 same-address atomicAdds serializing at
// ~27cyc each + last-block L2 re-read) is the largest reducible chunk.
// R3: each block release-stores ONE 64-bit word {flag | partial_bits} to a
// distinct slot; block 0 acquire-polls the slots (flag and value arrive in
// the same load). No membar, no atomics, fixed summation order.

#define NBLK 45
#define NTHR 128

__device__ unsigned long long g_slot[NBLK];   // zero-init; block0 re-zeros after use

__global__ __launch_bounds__(NTHR) void reward_criterion_kernel(
    const float* __restrict__ logp,
    const float* __restrict__ reward,
    const int*   __restrict__ tgt_raw,   // target buffer viewed as int32 words
    float* __restrict__ out,
    int N, int V)
{
    __shared__ float s_warp[NTHR / 32];
    __shared__ int   s_is64;

    const int tid  = threadIdx.x;
    const int lane = tid & 31;
    const int i    = blockIdx.x * NTHR + tid;

    // ---- detection loads issue concurrently with target/reward loads ----
    // int64 little-endian with values < V => every odd 32-bit word is zero.
    int detect_w = 0;
    if (tid < 32) detect_w = __ldg(&tgt_raw[2 * tid + 1]);

    float rw = 0.0f;
    if (i < N) rw = __ldg(&reward[i]);

    if (tid < 32) {
        unsigned nz = __ballot_sync(0xffffffffu, detect_w != 0);
        if (lane == 0) s_is64 = (nz == 0u) ? 1 : 0;
    }
    __syncthreads();
    const bool is64 = (s_is64 != 0);

    // ---- data-dependent gather (irreducible 2-deep load chain) ----
    float sum = 0.0f;
    if (i < N) {
        const int t = is64 ? __ldg(&tgt_raw[2 * i]) : __ldg(&tgt_raw[i]);
        sum = __ldg(&logp[(long long)i * (long long)V + t]) * rw;
    }

    // ---- block reduce (deterministic) ----
    #pragma unroll
    for (int off = 16; off > 0; off >>= 1)
        sum += __shfl_down_sync(0xffffffffu, sum, off);
    if (lane == 0) s_warp[tid >> 5] = sum;
    __syncthreads();

    if (tid < 32) {
        float v = (lane < NTHR / 32) ? s_warp[lane] : 0.0f;
        #pragma unroll
        for (int off = 2; off > 0; off >>= 1)
            v += __shfl_down_sync(0xffffffffu, v, off);

        // ---- publish: one release store carries flag + value ----
        if (lane == 0) {
            unsigned long long p =
                (1ULL << 32) | (unsigned long long)__float_as_uint(v);
            asm volatile("st.release.gpu.global.u64 [%0], %1;"
                         :: "l"(&g_slot[blockIdx.x]), "l"(p) : "memory");
        }

        // ---- block 0: poll slots, sum in FIXED order, re-arm ----
        if (blockIdx.x == 0) {
            float acc = 0.0f;
            for (int s = lane; s < NBLK; s += 32) {
                unsigned long long w;
                do {
                    asm volatile("ld.acquire.gpu.global.u64 %0, [%1];"
                                 : "=l"(w) : "l"(&g_slot[s]) : "memory");
                } while ((w >> 32) == 0ULL);
                acc += __uint_as_float((unsigned)w);
                g_slot[s] = 0ULL;   // re-arm for next graph replay
            }
            #pragma unroll
            for (int off = 16; off > 0; off >>= 1)
                acc += __shfl_down_sync(0xffffffffu, acc, off);
            if (lane == 0) out[0] = -acc;
        }
    }
}

extern "C" void kernel_launch(void* const* d_in, const int* in_sizes, int n_in,
                              void* d_out, int out_size)
{
    // metadata order: seqLogprobs, reward, batchsize_cap, target
    const float* logp    = (const float*)d_in[0];
    const float* reward  = (const float*)d_in[1];
    const int*   tgt_raw = (const int*)d_in[3];

    const int N = in_sizes[1];              // 5728
    const int V = in_sizes[0] / N;          // 9487

    reward_criterion_kernel<<<NBLK, NTHR>>>(logp, reward, tgt_raw,
                                            (float*)d_out, N, V);
}

// round 4
// speedup vs baseline: 1.3077x; 1.3077x over previous
#include <cuda_runtime.h>
#include <cuda_bf16.h>

// loss = -sum_i logp[i, target[i]] * reward[i]
//   logp:   (N, V) float32, N = 5728, V = 9487  (~217 MB)
//   reward: (N,)   float32
//   target: int64 OR int32 (JAX x64 ambiguity) -> runtime width detect
//
// R3 post-mortem: regression came from deepening the load chain to 3 DRAM
// latencies (detect -> sync -> target -> gather), not from the slot tail.
// R4 = R2's concurrent loads (chain depth 2) + the single-word release-slot
// tail (no membar, no atomics, no second L2 round trip). Deterministic:
// fixed summation order everywhere.

#define NBLK 45
#define NTHR 128

__device__ unsigned long long g_slot[NBLK];   // zero-init; block0 re-zeros after use

__global__ __launch_bounds__(NTHR) void reward_criterion_kernel(
    const float* __restrict__ logp,
    const float* __restrict__ reward,
    const int*   __restrict__ tgt_raw,   // target buffer viewed as int32 words
    float* __restrict__ out,
    int N, int V)
{
    __shared__ float s_warp[NTHR / 32];
    __shared__ int   s_is64;

    const int tid  = threadIdx.x;
    const int lane = tid & 31;
    const int i    = blockIdx.x * NTHR + tid;

    // ---- issue ALL first-round loads concurrently (detect + both widths) ----
    // int64 little-endian with values < V => every odd 32-bit word is zero.
    int detect_w = 0;
    if (tid < 32) detect_w = __ldg(&tgt_raw[2 * tid + 1]);

    int t32 = 0, t64 = 0;
    float rw = 0.0f;
    if (i < N) {
        t32 = __ldg(&tgt_raw[i]);          // int32 interpretation
        t64 = __ldg(&tgt_raw[2 * i]);      // int64-low-word interpretation
        rw  = __ldg(&reward[i]);
    }

    if (tid < 32) {
        unsigned nz = __ballot_sync(0xffffffffu, detect_w != 0);
        if (lane == 0) s_is64 = (nz == 0u) ? 1 : 0;
    }
    __syncthreads();
    const bool is64 = (s_is64 != 0);

    // ---- dependent gather (register select, loads already in flight) ----
    float sum = 0.0f;
    if (i < N) {
        const int t = is64 ? t64 : t32;
        sum = __ldg(&logp[(long long)i * (long long)V + t]) * rw;
    }

    // ---- block reduce (deterministic) ----
    #pragma unroll
    for (int off = 16; off > 0; off >>= 1)
        sum += __shfl_down_sync(0xffffffffu, sum, off);
    if (lane == 0) s_warp[tid >> 5] = sum;
    __syncthreads();

    if (tid < 32) {
        float v = (lane < NTHR / 32) ? s_warp[lane] : 0.0f;
        #pragma unroll
        for (int off = 2; off > 0; off >>= 1)
            v += __shfl_down_sync(0xffffffffu, v, off);

        // ---- publish: ONE release store carries flag + value ----
        if (lane == 0) {
            unsigned long long p =
                (1ULL << 32) | (unsigned long long)__float_as_uint(v);
            asm volatile("st.release.gpu.global.u64 [%0], %1;"
                         :: "l"(&g_slot[blockIdx.x]), "l"(p) : "memory");
        }

        // ---- block 0: poll slots, sum in FIXED order, re-arm ----
        if (blockIdx.x == 0) {
            float acc = 0.0f;
            for (int s = lane; s < NBLK; s += 32) {
                unsigned long long w;
                do {
                    asm volatile("ld.acquire.gpu.global.u64 %0, [%1];"
                                 : "=l"(w) : "l"(&g_slot[s]) : "memory");
                } while ((w >> 32) == 0ULL);
                acc += __uint_as_float((unsigned)w);
                g_slot[s] = 0ULL;   // re-arm for next graph replay
            }
            #pragma unroll
            for (int off = 16; off > 0; off >>= 1)
                acc += __shfl_down_sync(0xffffffffu, acc, off);
            if (lane == 0) out[0] = -acc;
        }
    }
}

extern "C" void kernel_launch(void* const* d_in, const int* in_sizes, int n_in,
                              void* d_out, int out_size)
{
    // metadata order: seqLogprobs, reward, batchsize_cap, target
    const float* logp    = (const float*)d_in[0];
    const float* reward  = (const float*)d_in[1];
    const int*   tgt_raw = (const int*)d_in[3];

    const int N = in_sizes[1];              // 5728
    const int V = in_sizes[0] / N;          // 9487

    reward_criterion_kernel<<<NBLK, NTHR>>>(logp, reward, tgt_raw,
                                            (float*)d_out, N, V);
}